// round 14
// baseline (speedup 1.0000x reference)
#include <cuda_runtime.h>
#include <cuda_fp16.h>
#include <math.h>
#include <stdint.h>

#define N_NODES  100000
#define N_EDGES  3200000
#define N_GRAPHS 512
#define HID      256
#define MIDC     128
#define OUTC     16
#define LN_EPS   1e-5f
#define NBLK     391                    // ceil(N_NODES/256)

// ---------------- scratch (device globals) -----------------------------------
__device__ __align__(16) __half g_hh[(size_t)N_NODES * HID];   // gemm output (fp16)
__device__ __align__(16) __half g_agg[(size_t)N_NODES * HID];  // layer-2 agg (fp16)
__device__ float  g_dinv[N_NODES];
__device__ int    g_degi[N_NODES];
__device__ int    g_cur[N_NODES];
__device__ int    g_off[N_NODES + 1];
__device__ int    g_bsum[NBLK];
__device__ int    g_boff[NBLK];
__device__ int    g_esrc[N_EDGES];            // src ids, sorted by dst
__device__ float  g_A[2 * N_NODES];           // rank-2 aggregate (layer 1)
__device__ double g_mA[5];                    // SA0,SA1,S00,S11,S01
__device__ __align__(16) float g_c0[HID];     // fused layer-1 affine constants
__device__ __align__(16) float g_c1[HID];
__device__ __align__(16) float g_c2[HID];
__device__ double g_red[2];                   // sum, sumsq (layer 2 LN)
__device__ __align__(16) float  g_pooled[N_GRAPHS * HID];
__device__ float  g_cnt[N_GRAPHS];
__device__ float  g_mid[N_GRAPHS * MIDC];
__device__ int    g_flag;                     // 1 = int32 input, 0 = int64
__device__ int    g_batch[N_NODES];

// ---------------- helpers ----------------------------------------------------
__device__ __forceinline__ void red_add_v4(float4* p, float x, float y, float z, float w) {
    asm volatile("red.global.add.v4.f32 [%0], {%1,%2,%3,%4};"
                 :: "l"(p), "f"(x), "f"(y), "f"(z), "f"(w) : "memory");
}
__device__ __forceinline__ int clampi(int v, int hi) {
    return v < 0 ? 0 : (v >= hi ? hi - 1 : v);
}
__device__ __forceinline__ void mma_f16(float* c, const uint32_t* a, const uint32_t* b) {
    asm("mma.sync.aligned.m16n8k16.row.col.f32.f16.f16.f32 "
        "{%0,%1,%2,%3}, {%4,%5,%6,%7}, {%8,%9}, {%0,%1,%2,%3};"
        : "+f"(c[0]), "+f"(c[1]), "+f"(c[2]), "+f"(c[3])
        : "r"(a[0]), "r"(a[1]), "r"(a[2]), "r"(a[3]), "r"(b[0]), "r"(b[1]));
}
// packed dual-FMA (sm_100+): c = a*b + c on two fp32 lanes
__device__ __forceinline__ void ffma2(float2& c, float2 a, float2 b) {
    unsigned long long cc = *(unsigned long long*)&c;
    unsigned long long aa = *(unsigned long long*)&a;
    unsigned long long bb = *(unsigned long long*)&b;
    asm("fma.rn.f32x2 %0, %1, %2, %3;" : "=l"(cc) : "l"(aa), "l"(bb), "l"(cc));
    c = *(float2*)&cc;
}

// ---------------- init / dtype / conversion ----------------------------------
__global__ void k_init() {
    int i = blockIdx.x * blockDim.x + threadIdx.x;
    if (i == 0) { g_flag = 0; g_red[0] = 0.0; g_red[1] = 0.0;
                  for (int k = 0; k < 5; k++) g_mA[k] = 0.0; }
    if (i < N_NODES) { g_degi[i] = 0; g_cur[i] = 0; }
    if (i < 2 * N_NODES) g_A[i] = 0.0f;
    if (i < N_GRAPHS * HID) g_pooled[i] = 0.0f;
    if (i < N_GRAPHS) g_cnt[i] = 0.0f;
}

__global__ void k_detect(const unsigned int* __restrict__ w) {
    int t = blockIdx.x * blockDim.x + threadIdx.x;         // 4096 threads
    long long idx = (long long)t * ((long long)N_EDGES / 4096);
    if (w[idx | 1] != 0u) atomicOr(&g_flag, 1);
}

// degree histogram, 2 edges/thread (decodes dst only)
__global__ void k_hist(const void* __restrict__ ei) {
    int i = blockIdx.x * blockDim.x + threadIdx.x;         // N_EDGES/2 threads
    if (i >= N_EDGES / 2) return;
    int d0, d1;
    if (g_flag) {
        int2 v = ((const int2*)((const int*)ei + N_EDGES))[i];
        d0 = v.x; d1 = v.y;
    } else {
        longlong2 v = ((const longlong2*)((const long long*)ei + N_EDGES))[i];
        d0 = (int)v.x; d1 = (int)v.y;
    }
    atomicAdd(&g_degi[clampi(d0, N_NODES)], 1);
    atomicAdd(&g_degi[clampi(d1, N_NODES)], 1);
}

__global__ void k_cvt_batch(const void* __restrict__ b) {
    int i = blockIdx.x * blockDim.x + threadIdx.x;
    if (i >= N_NODES) return;
    int v = g_flag ? ((const int*)b)[i] : (int)((const long long*)b)[i];
    g_batch[i] = clampi(v, N_GRAPHS);
}

// ---------------- CSR build (dinv fused into block scan) ----------------------
__global__ void k_scan_block() {
    __shared__ int sh[256];
    int t = threadIdx.x, i = blockIdx.x * 256 + t;
    int v = (i < N_NODES) ? g_degi[i] : 0;
    sh[t] = v; __syncthreads();
    for (int o = 1; o < 256; o <<= 1) {
        int x = (t >= o) ? sh[t - o] : 0;
        __syncthreads(); sh[t] += x; __syncthreads();
    }
    if (i < N_NODES) {
        g_off[i]  = sh[t] - v;
        g_dinv[i] = rsqrtf((float)v + 1.0f);     // +1: self loop
    }
    if (t == 255) g_bsum[blockIdx.x] = sh[255];
}

__global__ void k_scan_top() {
    __shared__ int sh[512];
    int t = threadIdx.x;
    int v = (t < NBLK) ? g_bsum[t] : 0;
    sh[t] = v; __syncthreads();
    for (int o = 1; o < 512; o <<= 1) {
        int x = (t >= o) ? sh[t - o] : 0;
        __syncthreads(); sh[t] += x; __syncthreads();
    }
    if (t < NBLK) g_boff[t] = sh[t] - v;
}

__global__ void k_scan_add() {
    int i = blockIdx.x * blockDim.x + threadIdx.x;
    if (i < N_NODES) g_off[i] += g_boff[i >> 8];
    if (i == 0) g_off[N_NODES] = N_EDGES;
}

// scatter edges (src only) by dst, 2 edges/thread; fused rank-2 pos aggregation
__global__ void k_scatter(const void* __restrict__ ei, const float* __restrict__ pos) {
    int i = blockIdx.x * blockDim.x + threadIdx.x;         // N_EDGES/2 threads
    if (i >= N_EDGES / 2) return;
    int s0, s1, d0, d1;
    if (g_flag) {
        const int* p = (const int*)ei;
        int2 sv = ((const int2*)p)[i];
        int2 dv = ((const int2*)(p + N_EDGES))[i];
        s0 = sv.x; s1 = sv.y; d0 = dv.x; d1 = dv.y;
    } else {
        const long long* p = (const long long*)ei;
        longlong2 sv = ((const longlong2*)p)[i];
        longlong2 dv = ((const longlong2*)(p + N_EDGES))[i];
        s0 = (int)sv.x; s1 = (int)sv.y; d0 = (int)dv.x; d1 = (int)dv.y;
    }
    s0 = clampi(s0, N_NODES); d0 = clampi(d0, N_NODES);
    s1 = clampi(s1, N_NODES); d1 = clampi(d1, N_NODES);
    {
        float nrm = g_dinv[s0] * g_dinv[d0];
        int p0 = g_off[d0] + atomicAdd(&g_cur[d0], 1);
        g_esrc[p0] = s0;
        atomicAdd(&g_A[2 * d0 + 0], nrm * pos[2 * s0]);
        atomicAdd(&g_A[2 * d0 + 1], nrm * pos[2 * s0 + 1]);
    }
    {
        float nrm = g_dinv[s1] * g_dinv[d1];
        int p1 = g_off[d1] + atomicAdd(&g_cur[d1], 1);
        g_esrc[p1] = s1;
        atomicAdd(&g_A[2 * d1 + 0], nrm * pos[2 * s1]);
        atomicAdd(&g_A[2 * d1 + 1], nrm * pos[2 * s1 + 1]);
    }
}

// self-loop term + node-moment reduction (fused)
__global__ void k_selfq(const float* __restrict__ pos) {
    int n = blockIdx.x * blockDim.x + threadIdx.x;
    float a0 = 0.f, a1 = 0.f;
    if (n < N_NODES) {
        float d = g_dinv[n], d2 = d * d;
        a0 = g_A[2 * n + 0] + d2 * pos[2 * n];
        a1 = g_A[2 * n + 1] + d2 * pos[2 * n + 1];
        g_A[2 * n + 0] = a0;
        g_A[2 * n + 1] = a1;
    }
    __shared__ float sh[5][256];
    int t = threadIdx.x;
    sh[0][t] = a0; sh[1][t] = a1; sh[2][t] = a0 * a0; sh[3][t] = a1 * a1; sh[4][t] = a0 * a1;
    __syncthreads();
    for (int o = 128; o > 0; o >>= 1) {
        if (t < o)
            for (int k = 0; k < 5; k++) sh[k][t] += sh[k][t + o];
        __syncthreads();
    }
    if (t == 0)
        for (int k = 0; k < 5; k++) atomicAdd(&g_mA[k], (double)sh[k][0]);
}

// ---------------- layer 1: analytic LN stats + fused affine constants --------
__global__ void k_stats1(const float* __restrict__ w, const float* __restrict__ b,
                         const float* __restrict__ lnw, const float* __restrict__ lnb) {
    __shared__ double sh[9][256];
    __shared__ float mstd[2];
    int c = threadIdx.x;
    double w0 = w[c], w1 = w[c + HID], bc = b[c];
    sh[0][c] = bc;        sh[1][c] = bc * bc;
    sh[2][c] = w0;        sh[3][c] = w1;
    sh[4][c] = w0 * w0;   sh[5][c] = w1 * w1;
    sh[6][c] = w0 * w1;   sh[7][c] = bc * w0;   sh[8][c] = bc * w1;
    __syncthreads();
    for (int o = 128; o > 0; o >>= 1) {
        if (c < o)
            for (int k = 0; k < 9; k++) sh[k][c] += sh[k][c + o];
        __syncthreads();
    }
    if (c == 0) {
        double Sb = sh[0][0], Sb2 = sh[1][0], SW0 = sh[2][0], SW1 = sh[3][0];
        double SW0q = sh[4][0], SW1q = sh[5][0], SW01 = sh[6][0];
        double SbW0 = sh[7][0], SbW1 = sh[8][0];
        double SA0 = g_mA[0], SA1 = g_mA[1], S00 = g_mA[2], S11 = g_mA[3], S01 = g_mA[4];
        double Nn = (double)N_NODES, NC = Nn * (double)HID;
        double sum = Nn * Sb + SA0 * SW0 + SA1 * SW1;
        double ss  = Nn * Sb2 + S00 * SW0q + S11 * SW1q
                   + 2.0 * (SA0 * SbW0 + SA1 * SbW1 + S01 * SW01);
        double mean = sum / NC;
        double var  = ss / NC - mean * mean;
        mstd[0] = (float)mean;
        mstd[1] = 1.0f / ((float)sqrt(var > 0.0 ? var : 0.0) + LN_EPS);
    }
    __syncthreads();
    float mean = mstd[0], inv = mstd[1];
    float lw = lnw[c], lb = lnb[c];
    g_c0[c] = ((float)b[c] - mean) * inv * lw + lb;
    g_c1[c] = (float)w[c]       * inv * lw;
    g_c2[c] = (float)w[c + HID] * inv * lw;
}

// ---------------- layer 2: fp16 tensor-core GEMM with fused A generation -----
__global__ void k_gemm(const float* __restrict__ W, const float* __restrict__ alpha) {
    __shared__ __half As[128][24];
    __shared__ __half Bs[128][24];
    const int M = N_NODES;
    const int t = threadIdx.x;
    const int lane = t & 31, warp = t >> 5;
    const int wr = warp >> 1, wc = warp & 1;
    const int g = lane >> 2, tig = lane & 3;
    const int bm = blockIdx.x * 128, bn = blockIdx.y * 128;

    float c[2][8][4];
    #pragma unroll
    for (int i = 0; i < 2; i++)
        #pragma unroll
        for (int j = 0; j < 8; j++)
            #pragma unroll
            for (int r = 0; r < 4; r++) c[i][j][r] = 0.0f;

    const int am = t >> 1, ak = (t & 1) * 8;
    const int bkk = t >> 4, bc = (t & 15) * 8;

    const int gr = bm + am;
    float A0 = 0.f, A1 = 0.f;
    if (gr < M) { A0 = g_A[2 * gr]; A1 = g_A[2 * gr + 1]; }
    const float pa = *alpha;

    for (int k0 = 0; k0 < 256; k0 += 16) {
        {
            const float4* C0 = (const float4*)(g_c0 + k0 + ak);
            const float4* C1 = (const float4*)(g_c1 + k0 + ak);
            const float4* C2 = (const float4*)(g_c2 + k0 + ak);
            float v[8];
            float4 x0 = C0[0], x1 = C0[1];
            float4 y0 = C1[0], y1 = C1[1];
            float4 z0 = C2[0], z1 = C2[1];
            v[0] = x0.x + A0 * y0.x + A1 * z0.x;
            v[1] = x0.y + A0 * y0.y + A1 * z0.y;
            v[2] = x0.z + A0 * y0.z + A1 * z0.z;
            v[3] = x0.w + A0 * y0.w + A1 * z0.w;
            v[4] = x1.x + A0 * y1.x + A1 * z1.x;
            v[5] = x1.y + A0 * y1.y + A1 * z1.y;
            v[6] = x1.z + A0 * y1.z + A1 * z1.z;
            v[7] = x1.w + A0 * y1.w + A1 * z1.w;
            #pragma unroll
            for (int i = 0; i < 8; i++) v[i] = (v[i] >= 0.f) ? v[i] : pa * v[i];
            __half2 h[4];
            #pragma unroll
            for (int i = 0; i < 4; i++) h[i] = __floats2half2_rn(v[2 * i], v[2 * i + 1]);
            *(int4*)&As[am][ak] = *(const int4*)h;
        }
        {
            const float4* p = (const float4*)(W + (size_t)(k0 + bkk) * 256 + bn + bc);
            float4 w0 = p[0], w1 = p[1];
            Bs[bc + 0][bkk] = __float2half(w0.x);
            Bs[bc + 1][bkk] = __float2half(w0.y);
            Bs[bc + 2][bkk] = __float2half(w0.z);
            Bs[bc + 3][bkk] = __float2half(w0.w);
            Bs[bc + 4][bkk] = __float2half(w1.x);
            Bs[bc + 5][bkk] = __float2half(w1.y);
            Bs[bc + 6][bkk] = __float2half(w1.z);
            Bs[bc + 7][bkk] = __float2half(w1.w);
        }
        __syncthreads();
        uint32_t a[2][4], b[8][2];
        #pragma unroll
        for (int i = 0; i < 2; i++) {
            int r0 = wr * 32 + i * 16 + g;
            a[i][0] = *(const uint32_t*)&As[r0][2 * tig];
            a[i][1] = *(const uint32_t*)&As[r0 + 8][2 * tig];
            a[i][2] = *(const uint32_t*)&As[r0][2 * tig + 8];
            a[i][3] = *(const uint32_t*)&As[r0 + 8][2 * tig + 8];
        }
        #pragma unroll
        for (int j = 0; j < 8; j++) {
            int cb = wc * 64 + j * 8 + g;
            b[j][0] = *(const uint32_t*)&Bs[cb][2 * tig];
            b[j][1] = *(const uint32_t*)&Bs[cb][2 * tig + 8];
        }
        #pragma unroll
        for (int i = 0; i < 2; i++)
            #pragma unroll
            for (int j = 0; j < 8; j++)
                mma_f16(c[i][j], a[i], b[j]);
        __syncthreads();
    }
    #pragma unroll
    for (int i = 0; i < 2; i++) {
        int r0 = bm + wr * 32 + i * 16 + g;
        int r1 = r0 + 8;
        #pragma unroll
        for (int j = 0; j < 8; j++) {
            int col = bn + wc * 64 + j * 8 + 2 * tig;
            if (r0 < M)
                *(__half2*)(g_hh + (size_t)r0 * 256 + col) = __floats2half2_rn(c[i][j][0], c[i][j][1]);
            if (r1 < M)
                *(__half2*)(g_hh + (size_t)r1 * 256 + col) = __floats2half2_rn(c[i][j][2], c[i][j][3]);
        }
    }
}

// CSR aggregation: 4 consecutive nodes per warp (load-balance + contiguous
// g_esrc ranges), fp16 gather, packed f32x2 accum, fp16 out, LN stats epilogue
__global__ void k_agg2(const float* __restrict__ bias) {
    int wg = (blockIdx.x * blockDim.x + threadIdx.x) >> 5;   // warp id: 0..24999
    int lane = threadIdx.x & 31;
    // bias channels for this lane (reused across the 4 nodes)
    float2 bch[4];
    {
        const float4* b4 = (const float4*)(bias + lane * 8);
        float4 x = b4[0], y = b4[1];
        bch[0] = make_float2(x.x, x.y); bch[1] = make_float2(x.z, x.w);
        bch[2] = make_float2(y.x, y.y); bch[3] = make_float2(y.z, y.w);
    }
    float s = 0.f, s2 = 0.f;
    #pragma unroll
    for (int q = 0; q < 4; q++) {
        int n = wg * 4 + q;
        float dn = g_dinv[n];
        float2 acc[4] = { bch[0], bch[1], bch[2], bch[3] };
        {   // self loop
            float d2 = dn * dn;
            float2 d2v = make_float2(d2, d2);
            int4 v = ((const int4*)(g_hh + (size_t)n * HID))[lane];
            const __half2* h = (const __half2*)&v;
            #pragma unroll
            for (int i = 0; i < 4; i++) ffma2(acc[i], __half22float2(h[i]), d2v);
        }
        int e = g_off[n], e1 = g_off[n + 1];
        for (; e + 1 < e1; e += 2) {
            int sa = g_esrc[e], sb = g_esrc[e + 1];
            float2 fa = make_float2(g_dinv[sa] * dn, g_dinv[sa] * dn);
            float2 fb = make_float2(g_dinv[sb] * dn, g_dinv[sb] * dn);
            int4 va = ((const int4*)(g_hh + (size_t)sa * HID))[lane];
            int4 vb = ((const int4*)(g_hh + (size_t)sb * HID))[lane];
            const __half2* ha = (const __half2*)&va;
            const __half2* hb = (const __half2*)&vb;
            #pragma unroll
            for (int i = 0; i < 4; i++) {
                ffma2(acc[i], __half22float2(ha[i]), fa);
                ffma2(acc[i], __half22float2(hb[i]), fb);
            }
        }
        if (e < e1) {
            int sa = g_esrc[e];
            float2 fa = make_float2(g_dinv[sa] * dn, g_dinv[sa] * dn);
            int4 va = ((const int4*)(g_hh + (size_t)sa * HID))[lane];
            const __half2* ha = (const __half2*)&va;
            #pragma unroll
            for (int i = 0; i < 4; i++) ffma2(acc[i], __half22float2(ha[i]), fa);
        }
        {   // write agg as fp16
            __half2 h[4];
            #pragma unroll
            for (int i = 0; i < 4; i++) h[i] = __floats2half2_rn(acc[i].x, acc[i].y);
            ((int4*)(g_agg + (size_t)n * HID))[lane] = *(const int4*)h;
        }
        #pragma unroll
        for (int i = 0; i < 4; i++) {
            s  += acc[i].x + acc[i].y;
            s2 += acc[i].x * acc[i].x + acc[i].y * acc[i].y;
        }
    }
    for (int o = 16; o > 0; o >>= 1) {
        s  += __shfl_xor_sync(0xffffffffu, s,  o);
        s2 += __shfl_xor_sync(0xffffffffu, s2, o);
    }
    __shared__ float sh[2][8];
    int w = threadIdx.x >> 5;
    if (lane == 0) { sh[0][w] = s; sh[1][w] = s2; }
    __syncthreads();
    if (threadIdx.x == 0) {
        float ts = 0.f, ts2 = 0.f;
        #pragma unroll
        for (int i = 0; i < 8; i++) { ts += sh[0][i]; ts2 += sh[1][i]; }
        atomicAdd(&g_red[0], (double)ts);
        atomicAdd(&g_red[1], (double)ts2);
    }
}

// fused LN2 + PReLU + mean-pool scatter (stats derived inline from g_red)
__global__ void k_pool_ln(const float* __restrict__ lnw, const float* __restrict__ lnb,
                          const float* __restrict__ alpha) {
    int t = blockIdx.x * blockDim.x + threadIdx.x;
    int n = t >> 5;
    if (n >= N_NODES) return;
    int lane = t & 31;
    double NC = (double)N_NODES * (double)HID;
    double mean_d = g_red[0] / NC;
    double var_d  = g_red[1] / NC - mean_d * mean_d;
    float mean = (float)mean_d;
    float inv  = 1.0f / ((float)sqrt(var_d > 0.0 ? var_d : 0.0) + LN_EPS);
    float a = *alpha;
    int4 v = ((const int4*)(g_agg + (size_t)n * HID))[lane];
    const __half2* h = (const __half2*)&v;
    const float4* w4 = (const float4*)(lnw + lane * 8);
    const float4* b4 = (const float4*)(lnb + lane * 8);
    float4 w0 = w4[0], w1 = w4[1];
    float4 c0 = b4[0], c1 = b4[1];
    float x[8];
    #pragma unroll
    for (int i = 0; i < 4; i++) {
        float2 f = __half22float2(h[i]);
        x[2 * i] = f.x; x[2 * i + 1] = f.y;
    }
    float r[8];
    r[0] = (x[0] - mean) * inv * w0.x + c0.x;
    r[1] = (x[1] - mean) * inv * w0.y + c0.y;
    r[2] = (x[2] - mean) * inv * w0.z + c0.z;
    r[3] = (x[3] - mean) * inv * w0.w + c0.w;
    r[4] = (x[4] - mean) * inv * w1.x + c1.x;
    r[5] = (x[5] - mean) * inv * w1.y + c1.y;
    r[6] = (x[6] - mean) * inv * w1.z + c1.z;
    r[7] = (x[7] - mean) * inv * w1.w + c1.w;
    #pragma unroll
    for (int i = 0; i < 8; i++) r[i] = (r[i] >= 0.0f) ? r[i] : a * r[i];
    float4* p = (float4*)(g_pooled + (size_t)g_batch[n] * HID + lane * 8);
    red_add_v4(p,     r[0], r[1], r[2], r[3]);
    red_add_v4(p + 1, r[4], r[5], r[6], r[7]);
    if (lane == 0) atomicAdd(&g_cnt[g_batch[n]], 1.0f);
}

// ---------------- pooled MLP --------------------------------------------------
__global__ void k_lin1(const float* __restrict__ W, const float* __restrict__ bias) {
    int t = blockIdx.x * blockDim.x + threadIdx.x;   // 512*128
    int g = t >> 7, j = t & 127;
    const float* row = g_pooled + (size_t)g * HID;
    float s = 0.0f;
    #pragma unroll 8
    for (int c = 0; c < HID; c++) s += row[c] * W[(size_t)c * MIDC + j];
    g_mid[t] = s / fmaxf(g_cnt[g], 1.0f) + bias[j];
}

__global__ void k_ln_mid(const float* __restrict__ w, const float* __restrict__ b,
                         const float* __restrict__ alpha) {
    const int n = N_GRAPHS * MIDC;
    float a = *alpha;
    float s = 0.0f, s2 = 0.0f;
    for (int i = threadIdx.x; i < n; i += blockDim.x) {
        float v = g_mid[i]; s += v; s2 += v * v;
    }
    for (int o = 16; o > 0; o >>= 1) {
        s  += __shfl_xor_sync(0xffffffffu, s,  o);
        s2 += __shfl_xor_sync(0xffffffffu, s2, o);
    }
    __shared__ float sh[2][32];
    __shared__ float mstd[2];
    int wr = threadIdx.x >> 5, l = threadIdx.x & 31;
    if (l == 0) { sh[0][wr] = s; sh[1][wr] = s2; }
    __syncthreads();
    if (threadIdx.x == 0) {
        float ts = 0.0f, ts2 = 0.0f;
        int nw = blockDim.x >> 5;
        for (int i = 0; i < nw; i++) { ts += sh[0][i]; ts2 += sh[1][i]; }
        float mean = ts / n;
        float var  = ts2 / n - mean * mean;
        mstd[0] = mean;
        mstd[1] = 1.0f / (sqrtf(fmaxf(var, 0.0f)) + LN_EPS);
    }
    __syncthreads();
    float mean = mstd[0], inv = mstd[1];
    for (int i = threadIdx.x; i < n; i += blockDim.x) {
        int c = i & (MIDC - 1);
        float v = (g_mid[i] - mean) * inv * w[c] + b[c];
        g_mid[i] = (v >= 0.0f) ? v : a * v;
    }
}

__global__ void k_lin2(const float* __restrict__ W, const float* __restrict__ bias,
                       float* __restrict__ out) {
    int t = blockIdx.x * blockDim.x + threadIdx.x;   // 512*16
    int g = t >> 4, o = t & 15;
    const float* row = g_mid + (size_t)g * MIDC;
    float s = 0.0f;
    #pragma unroll 8
    for (int j = 0; j < MIDC; j++) s += row[j] * W[(size_t)j * OUTC + o];
    out[t] = s + bias[o];
}

// ---------------- launch -----------------------------------------------------
extern "C" void kernel_launch(void* const* d_in, const int* in_sizes, int n_in,
                              void* d_out, int out_size) {
    const float* pos    = (const float*)d_in[0];
    const void*  ei     = d_in[1];
    const void*  batch  = d_in[2];
    const float* w_conv1 = (const float*)d_in[3];
    const float* b_conv1 = (const float*)d_in[4];
    const float* ln1_w   = (const float*)d_in[5];
    const float* ln1_b   = (const float*)d_in[6];
    const float* a1      = (const float*)d_in[7];
    const float* w_conv2 = (const float*)d_in[8];
    const float* b_conv2 = (const float*)d_in[9];
    const float* ln2_w   = (const float*)d_in[10];
    const float* ln2_b   = (const float*)d_in[11];
    const float* a2      = (const float*)d_in[12];
    const float* w_lin1  = (const float*)d_in[13];
    const float* b_lin1  = (const float*)d_in[14];
    const float* lnm_w   = (const float*)d_in[15];
    const float* lnm_b   = (const float*)d_in[16];
    const float* am      = (const float*)d_in[17];
    const float* w_lin2  = (const float*)d_in[18];
    const float* b_lin2  = (const float*)d_in[19];
    float* out = (float*)d_out;

    // init + dtype detect + histogram + batch conversion
    k_init<<<(2 * N_NODES + 255) / 256, 256>>>();
    k_detect<<<16, 256>>>((const unsigned int*)ei);
    k_hist<<<(N_EDGES / 2 + 255) / 256, 256>>>(ei);
    k_cvt_batch<<<(N_NODES + 255) / 256, 256>>>(batch);

    // CSR build (dinv fused into scan) + rank-2 layer-1 aggregation
    k_scan_block<<<NBLK, 256>>>();
    k_scan_top<<<1, 512>>>();
    k_scan_add<<<NBLK, 256>>>();
    k_scatter<<<(N_EDGES / 2 + 255) / 256, 256>>>(ei, pos);
    k_selfq<<<NBLK, 256>>>(pos);

    // layer 1: analytic LN stats -> fused affine constants
    k_stats1<<<1, 256>>>(w_conv1, b_conv1, ln1_w, ln1_b);

    // layer 2: GEMM with fused A generation, then fp16 CSR aggregation
    k_gemm<<<dim3((N_NODES + 127) / 128, 2), 256>>>(w_conv2, a1);
    k_agg2<<<(N_NODES / 4) * 32 / 256, 256>>>(b_conv2);

    // fused LN2 + PReLU + pooling, then MLP
    k_pool_ln<<<(N_NODES * 32 + 255) / 256, 256>>>(ln2_w, ln2_b, a2);
    k_lin1<<<(N_GRAPHS * MIDC) / 256, 256>>>(w_lin1, b_lin1);
    k_ln_mid<<<1, 1024>>>(lnm_w, lnm_b, am);
    k_lin2<<<(N_GRAPHS * OUTC) / 256, 256>>>(w_lin2, b_lin2, out);
}

// round 15
// speedup vs baseline: 1.0239x; 1.0239x over previous
#include <cuda_runtime.h>
#include <cuda_fp16.h>
#include <math.h>
#include <stdint.h>

#define N_NODES  100000
#define N_EDGES  3200000
#define N_GRAPHS 512
#define HID      256
#define MIDC     128
#define OUTC     16
#define LN_EPS   1e-5f
#define NBLK     391                    // ceil(N_NODES/256)

// ---------------- scratch (device globals) -----------------------------------
__device__ __align__(16) __half g_hh[(size_t)N_NODES * HID];   // gemm output (fp16)
__device__ __align__(16) __half g_agg[(size_t)N_NODES * HID];  // layer-2 agg (fp16)
__device__ float  g_dinv[N_NODES];
__device__ int    g_degi[N_NODES];
__device__ int    g_cur[N_NODES];
__device__ int    g_off[N_NODES + 1];
__device__ int    g_bsum[NBLK];
__device__ int    g_boff[NBLK];
__device__ int    g_esrc[N_EDGES];            // src ids, sorted by dst
__device__ float  g_A[2 * N_NODES];           // rank-2 aggregate (layer 1)
__device__ double g_mA[5];                    // SA0,SA1,S00,S11,S01
__device__ __align__(16) float g_c0[HID];     // fused layer-1 affine constants
__device__ __align__(16) float g_c1[HID];
__device__ __align__(16) float g_c2[HID];
__device__ double g_red[2];                   // sum, sumsq (layer 2 LN)
__device__ __align__(16) float  g_pooled[N_GRAPHS * HID];
__device__ float  g_cnt[N_GRAPHS];
__device__ float  g_mid[N_GRAPHS * MIDC];
__device__ int    g_flag;                     // 1 = int32 input, 0 = int64
__device__ int    g_batch[N_NODES];

// ---------------- helpers ----------------------------------------------------
__device__ __forceinline__ void red_add_v4(float4* p, float x, float y, float z, float w) {
    asm volatile("red.global.add.v4.f32 [%0], {%1,%2,%3,%4};"
                 :: "l"(p), "f"(x), "f"(y), "f"(z), "f"(w) : "memory");
}
__device__ __forceinline__ int clampi(int v, int hi) {
    return v < 0 ? 0 : (v >= hi ? hi - 1 : v);
}
__device__ __forceinline__ void mma_f16(float* c, const uint32_t* a, const uint32_t* b) {
    asm("mma.sync.aligned.m16n8k16.row.col.f32.f16.f16.f32 "
        "{%0,%1,%2,%3}, {%4,%5,%6,%7}, {%8,%9}, {%0,%1,%2,%3};"
        : "+f"(c[0]), "+f"(c[1]), "+f"(c[2]), "+f"(c[3])
        : "r"(a[0]), "r"(a[1]), "r"(a[2]), "r"(a[3]), "r"(b[0]), "r"(b[1]));
}
// packed dual-FMA (sm_100+): c = a*b + c on two fp32 lanes
__device__ __forceinline__ void ffma2(float2& c, float2 a, float2 b) {
    unsigned long long cc = *(unsigned long long*)&c;
    unsigned long long aa = *(unsigned long long*)&a;
    unsigned long long bb = *(unsigned long long*)&b;
    asm("fma.rn.f32x2 %0, %1, %2, %3;" : "=l"(cc) : "l"(aa), "l"(bb), "l"(cc));
    c = *(float2*)&cc;
}

// ---------------- init / dtype / conversion ----------------------------------
__global__ void k_init() {
    int i = blockIdx.x * blockDim.x + threadIdx.x;
    if (i == 0) { g_flag = 0; g_red[0] = 0.0; g_red[1] = 0.0;
                  for (int k = 0; k < 5; k++) g_mA[k] = 0.0; }
    if (i < N_NODES) { g_degi[i] = 0; g_cur[i] = 0; }
    if (i < 2 * N_NODES) g_A[i] = 0.0f;
    if (i < N_GRAPHS * HID) g_pooled[i] = 0.0f;
    if (i < N_GRAPHS) g_cnt[i] = 0.0f;
}

__global__ void k_detect(const unsigned int* __restrict__ w) {
    int t = blockIdx.x * blockDim.x + threadIdx.x;         // 4096 threads
    long long idx = (long long)t * ((long long)N_EDGES / 4096);
    if (w[idx | 1] != 0u) atomicOr(&g_flag, 1);
}

// degree histogram, 2 edges/thread (decodes dst only)
__global__ void k_hist(const void* __restrict__ ei) {
    int i = blockIdx.x * blockDim.x + threadIdx.x;         // N_EDGES/2 threads
    if (i >= N_EDGES / 2) return;
    int d0, d1;
    if (g_flag) {
        int2 v = ((const int2*)((const int*)ei + N_EDGES))[i];
        d0 = v.x; d1 = v.y;
    } else {
        longlong2 v = ((const longlong2*)((const long long*)ei + N_EDGES))[i];
        d0 = (int)v.x; d1 = (int)v.y;
    }
    atomicAdd(&g_degi[clampi(d0, N_NODES)], 1);
    atomicAdd(&g_degi[clampi(d1, N_NODES)], 1);
}

__global__ void k_cvt_batch(const void* __restrict__ b) {
    int i = blockIdx.x * blockDim.x + threadIdx.x;
    if (i >= N_NODES) return;
    int v = g_flag ? ((const int*)b)[i] : (int)((const long long*)b)[i];
    g_batch[i] = clampi(v, N_GRAPHS);
}

// ---------------- CSR build (dinv fused into block scan) ----------------------
__global__ void k_scan_block() {
    __shared__ int sh[256];
    int t = threadIdx.x, i = blockIdx.x * 256 + t;
    int v = (i < N_NODES) ? g_degi[i] : 0;
    sh[t] = v; __syncthreads();
    for (int o = 1; o < 256; o <<= 1) {
        int x = (t >= o) ? sh[t - o] : 0;
        __syncthreads(); sh[t] += x; __syncthreads();
    }
    if (i < N_NODES) {
        g_off[i]  = sh[t] - v;
        g_dinv[i] = rsqrtf((float)v + 1.0f);     // +1: self loop
    }
    if (t == 255) g_bsum[blockIdx.x] = sh[255];
}

__global__ void k_scan_top() {
    __shared__ int sh[512];
    int t = threadIdx.x;
    int v = (t < NBLK) ? g_bsum[t] : 0;
    sh[t] = v; __syncthreads();
    for (int o = 1; o < 512; o <<= 1) {
        int x = (t >= o) ? sh[t - o] : 0;
        __syncthreads(); sh[t] += x; __syncthreads();
    }
    if (t < NBLK) g_boff[t] = sh[t] - v;
}

__global__ void k_scan_add() {
    int i = blockIdx.x * blockDim.x + threadIdx.x;
    if (i < N_NODES) g_off[i] += g_boff[i >> 8];
    if (i == 0) g_off[N_NODES] = N_EDGES;
}

// scatter edges (src only) by dst, 2 edges/thread; fused rank-2 pos aggregation
__global__ void k_scatter(const void* __restrict__ ei, const float* __restrict__ pos) {
    int i = blockIdx.x * blockDim.x + threadIdx.x;         // N_EDGES/2 threads
    if (i >= N_EDGES / 2) return;
    int s0, s1, d0, d1;
    if (g_flag) {
        const int* p = (const int*)ei;
        int2 sv = ((const int2*)p)[i];
        int2 dv = ((const int2*)(p + N_EDGES))[i];
        s0 = sv.x; s1 = sv.y; d0 = dv.x; d1 = dv.y;
    } else {
        const long long* p = (const long long*)ei;
        longlong2 sv = ((const longlong2*)p)[i];
        longlong2 dv = ((const longlong2*)(p + N_EDGES))[i];
        s0 = (int)sv.x; s1 = (int)sv.y; d0 = (int)dv.x; d1 = (int)dv.y;
    }
    s0 = clampi(s0, N_NODES); d0 = clampi(d0, N_NODES);
    s1 = clampi(s1, N_NODES); d1 = clampi(d1, N_NODES);
    {
        float nrm = g_dinv[s0] * g_dinv[d0];
        int p0 = g_off[d0] + atomicAdd(&g_cur[d0], 1);
        g_esrc[p0] = s0;
        atomicAdd(&g_A[2 * d0 + 0], nrm * pos[2 * s0]);
        atomicAdd(&g_A[2 * d0 + 1], nrm * pos[2 * s0 + 1]);
    }
    {
        float nrm = g_dinv[s1] * g_dinv[d1];
        int p1 = g_off[d1] + atomicAdd(&g_cur[d1], 1);
        g_esrc[p1] = s1;
        atomicAdd(&g_A[2 * d1 + 0], nrm * pos[2 * s1]);
        atomicAdd(&g_A[2 * d1 + 1], nrm * pos[2 * s1 + 1]);
    }
}

// self-loop term + node-moment reduction (fused)
__global__ void k_selfq(const float* __restrict__ pos) {
    int n = blockIdx.x * blockDim.x + threadIdx.x;
    float a0 = 0.f, a1 = 0.f;
    if (n < N_NODES) {
        float d = g_dinv[n], d2 = d * d;
        a0 = g_A[2 * n + 0] + d2 * pos[2 * n];
        a1 = g_A[2 * n + 1] + d2 * pos[2 * n + 1];
        g_A[2 * n + 0] = a0;
        g_A[2 * n + 1] = a1;
    }
    __shared__ float sh[5][256];
    int t = threadIdx.x;
    sh[0][t] = a0; sh[1][t] = a1; sh[2][t] = a0 * a0; sh[3][t] = a1 * a1; sh[4][t] = a0 * a1;
    __syncthreads();
    for (int o = 128; o > 0; o >>= 1) {
        if (t < o)
            for (int k = 0; k < 5; k++) sh[k][t] += sh[k][t + o];
        __syncthreads();
    }
    if (t == 0)
        for (int k = 0; k < 5; k++) atomicAdd(&g_mA[k], (double)sh[k][0]);
}

// ---------------- layer 1: analytic LN stats + fused affine constants --------
__global__ void k_stats1(const float* __restrict__ w, const float* __restrict__ b,
                         const float* __restrict__ lnw, const float* __restrict__ lnb) {
    __shared__ double sh[9][256];
    __shared__ float mstd[2];
    int c = threadIdx.x;
    double w0 = w[c], w1 = w[c + HID], bc = b[c];
    sh[0][c] = bc;        sh[1][c] = bc * bc;
    sh[2][c] = w0;        sh[3][c] = w1;
    sh[4][c] = w0 * w0;   sh[5][c] = w1 * w1;
    sh[6][c] = w0 * w1;   sh[7][c] = bc * w0;   sh[8][c] = bc * w1;
    __syncthreads();
    for (int o = 128; o > 0; o >>= 1) {
        if (c < o)
            for (int k = 0; k < 9; k++) sh[k][c] += sh[k][c + o];
        __syncthreads();
    }
    if (c == 0) {
        double Sb = sh[0][0], Sb2 = sh[1][0], SW0 = sh[2][0], SW1 = sh[3][0];
        double SW0q = sh[4][0], SW1q = sh[5][0], SW01 = sh[6][0];
        double SbW0 = sh[7][0], SbW1 = sh[8][0];
        double SA0 = g_mA[0], SA1 = g_mA[1], S00 = g_mA[2], S11 = g_mA[3], S01 = g_mA[4];
        double Nn = (double)N_NODES, NC = Nn * (double)HID;
        double sum = Nn * Sb + SA0 * SW0 + SA1 * SW1;
        double ss  = Nn * Sb2 + S00 * SW0q + S11 * SW1q
                   + 2.0 * (SA0 * SbW0 + SA1 * SbW1 + S01 * SW01);
        double mean = sum / NC;
        double var  = ss / NC - mean * mean;
        mstd[0] = (float)mean;
        mstd[1] = 1.0f / ((float)sqrt(var > 0.0 ? var : 0.0) + LN_EPS);
    }
    __syncthreads();
    float mean = mstd[0], inv = mstd[1];
    float lw = lnw[c], lb = lnb[c];
    g_c0[c] = ((float)b[c] - mean) * inv * lw + lb;
    g_c1[c] = (float)w[c]       * inv * lw;
    g_c2[c] = (float)w[c + HID] * inv * lw;
}

// ---------------- layer 2: fp16 tensor-core GEMM with fused A generation -----
__global__ void k_gemm(const float* __restrict__ W, const float* __restrict__ alpha) {
    __shared__ __half As[128][24];
    __shared__ __half Bs[128][24];
    const int M = N_NODES;
    const int t = threadIdx.x;
    const int lane = t & 31, warp = t >> 5;
    const int wr = warp >> 1, wc = warp & 1;
    const int g = lane >> 2, tig = lane & 3;
    const int bm = blockIdx.x * 128, bn = blockIdx.y * 128;

    float c[2][8][4];
    #pragma unroll
    for (int i = 0; i < 2; i++)
        #pragma unroll
        for (int j = 0; j < 8; j++)
            #pragma unroll
            for (int r = 0; r < 4; r++) c[i][j][r] = 0.0f;

    const int am = t >> 1, ak = (t & 1) * 8;
    const int bkk = t >> 4, bc = (t & 15) * 8;

    const int gr = bm + am;
    float A0 = 0.f, A1 = 0.f;
    if (gr < M) { A0 = g_A[2 * gr]; A1 = g_A[2 * gr + 1]; }
    const float pa = *alpha;

    for (int k0 = 0; k0 < 256; k0 += 16) {
        {
            const float4* C0 = (const float4*)(g_c0 + k0 + ak);
            const float4* C1 = (const float4*)(g_c1 + k0 + ak);
            const float4* C2 = (const float4*)(g_c2 + k0 + ak);
            float v[8];
            float4 x0 = C0[0], x1 = C0[1];
            float4 y0 = C1[0], y1 = C1[1];
            float4 z0 = C2[0], z1 = C2[1];
            v[0] = x0.x + A0 * y0.x + A1 * z0.x;
            v[1] = x0.y + A0 * y0.y + A1 * z0.y;
            v[2] = x0.z + A0 * y0.z + A1 * z0.z;
            v[3] = x0.w + A0 * y0.w + A1 * z0.w;
            v[4] = x1.x + A0 * y1.x + A1 * z1.x;
            v[5] = x1.y + A0 * y1.y + A1 * z1.y;
            v[6] = x1.z + A0 * y1.z + A1 * z1.z;
            v[7] = x1.w + A0 * y1.w + A1 * z1.w;
            #pragma unroll
            for (int i = 0; i < 8; i++) v[i] = (v[i] >= 0.f) ? v[i] : pa * v[i];
            __half2 h[4];
            #pragma unroll
            for (int i = 0; i < 4; i++) h[i] = __floats2half2_rn(v[2 * i], v[2 * i + 1]);
            *(int4*)&As[am][ak] = *(const int4*)h;
        }
        {
            const float4* p = (const float4*)(W + (size_t)(k0 + bkk) * 256 + bn + bc);
            float4 w0 = p[0], w1 = p[1];
            Bs[bc + 0][bkk] = __float2half(w0.x);
            Bs[bc + 1][bkk] = __float2half(w0.y);
            Bs[bc + 2][bkk] = __float2half(w0.z);
            Bs[bc + 3][bkk] = __float2half(w0.w);
            Bs[bc + 4][bkk] = __float2half(w1.x);
            Bs[bc + 5][bkk] = __float2half(w1.y);
            Bs[bc + 6][bkk] = __float2half(w1.z);
            Bs[bc + 7][bkk] = __float2half(w1.w);
        }
        __syncthreads();
        uint32_t a[2][4], b[8][2];
        #pragma unroll
        for (int i = 0; i < 2; i++) {
            int r0 = wr * 32 + i * 16 + g;
            a[i][0] = *(const uint32_t*)&As[r0][2 * tig];
            a[i][1] = *(const uint32_t*)&As[r0 + 8][2 * tig];
            a[i][2] = *(const uint32_t*)&As[r0][2 * tig + 8];
            a[i][3] = *(const uint32_t*)&As[r0 + 8][2 * tig + 8];
        }
        #pragma unroll
        for (int j = 0; j < 8; j++) {
            int cb = wc * 64 + j * 8 + g;
            b[j][0] = *(const uint32_t*)&Bs[cb][2 * tig];
            b[j][1] = *(const uint32_t*)&Bs[cb][2 * tig + 8];
        }
        #pragma unroll
        for (int i = 0; i < 2; i++)
            #pragma unroll
            for (int j = 0; j < 8; j++)
                mma_f16(c[i][j], a[i], b[j]);
        __syncthreads();
    }
    #pragma unroll
    for (int i = 0; i < 2; i++) {
        int r0 = bm + wr * 32 + i * 16 + g;
        int r1 = r0 + 8;
        #pragma unroll
        for (int j = 0; j < 8; j++) {
            int col = bn + wc * 64 + j * 8 + 2 * tig;
            if (r0 < M)
                *(__half2*)(g_hh + (size_t)r0 * 256 + col) = __floats2half2_rn(c[i][j][0], c[i][j][1]);
            if (r1 < M)
                *(__half2*)(g_hh + (size_t)r1 * 256 + col) = __floats2half2_rn(c[i][j][2], c[i][j][3]);
        }
    }
}

// CSR aggregation: warp per node (proven layout), 4-edge unrolled gather for
// MLP=4, fp16 gather, f32x2 accum, fp16 out, LN stats epilogue
__global__ void k_agg2(const float* __restrict__ bias) {
    int t = blockIdx.x * blockDim.x + threadIdx.x;
    int n = t >> 5;                              // 12500 blocks x 8 warps exact
    int lane = t & 31;
    float dn = g_dinv[n];
    float2 acc[4];
    {
        const float4* b4 = (const float4*)(bias + lane * 8);
        float4 x = b4[0], y = b4[1];
        acc[0] = make_float2(x.x, x.y); acc[1] = make_float2(x.z, x.w);
        acc[2] = make_float2(y.x, y.y); acc[3] = make_float2(y.z, y.w);
    }
    {   // self loop
        float d2 = dn * dn;
        float2 d2v = make_float2(d2, d2);
        int4 v = ((const int4*)(g_hh + (size_t)n * HID))[lane];
        const __half2* h = (const __half2*)&v;
        #pragma unroll
        for (int i = 0; i < 4; i++) ffma2(acc[i], __half22float2(h[i]), d2v);
    }
    int e = g_off[n], e1 = g_off[n + 1];
    for (; e + 3 < e1; e += 4) {                 // 4 independent gathers in flight
        int sa = g_esrc[e],     sb = g_esrc[e + 1];
        int sc = g_esrc[e + 2], sd = g_esrc[e + 3];
        int4 va = ((const int4*)(g_hh + (size_t)sa * HID))[lane];
        int4 vb = ((const int4*)(g_hh + (size_t)sb * HID))[lane];
        int4 vc = ((const int4*)(g_hh + (size_t)sc * HID))[lane];
        int4 vd = ((const int4*)(g_hh + (size_t)sd * HID))[lane];
        float fa = g_dinv[sa] * dn, fb = g_dinv[sb] * dn;
        float fc = g_dinv[sc] * dn, fd = g_dinv[sd] * dn;
        float2 fa2 = make_float2(fa, fa), fb2 = make_float2(fb, fb);
        float2 fc2 = make_float2(fc, fc), fd2 = make_float2(fd, fd);
        const __half2* ha = (const __half2*)&va;
        const __half2* hb = (const __half2*)&vb;
        const __half2* hc = (const __half2*)&vc;
        const __half2* hd = (const __half2*)&vd;
        #pragma unroll
        for (int i = 0; i < 4; i++) {
            ffma2(acc[i], __half22float2(ha[i]), fa2);
            ffma2(acc[i], __half22float2(hb[i]), fb2);
            ffma2(acc[i], __half22float2(hc[i]), fc2);
            ffma2(acc[i], __half22float2(hd[i]), fd2);
        }
    }
    for (; e < e1; e++) {
        int sa = g_esrc[e];
        float fa = g_dinv[sa] * dn;
        float2 fa2 = make_float2(fa, fa);
        int4 va = ((const int4*)(g_hh + (size_t)sa * HID))[lane];
        const __half2* ha = (const __half2*)&va;
        #pragma unroll
        for (int i = 0; i < 4; i++) ffma2(acc[i], __half22float2(ha[i]), fa2);
    }
    {   // write agg as fp16
        __half2 h[4];
        #pragma unroll
        for (int i = 0; i < 4; i++) h[i] = __floats2half2_rn(acc[i].x, acc[i].y);
        ((int4*)(g_agg + (size_t)n * HID))[lane] = *(const int4*)h;
    }
    float s = 0.f, s2 = 0.f;
    #pragma unroll
    for (int i = 0; i < 4; i++) {
        s  += acc[i].x + acc[i].y;
        s2 += acc[i].x * acc[i].x + acc[i].y * acc[i].y;
    }
    for (int o = 16; o > 0; o >>= 1) {
        s  += __shfl_xor_sync(0xffffffffu, s,  o);
        s2 += __shfl_xor_sync(0xffffffffu, s2, o);
    }
    __shared__ float sh[2][8];
    int w = threadIdx.x >> 5;
    if (lane == 0) { sh[0][w] = s; sh[1][w] = s2; }
    __syncthreads();
    if (threadIdx.x == 0) {
        float ts = 0.f, ts2 = 0.f;
        #pragma unroll
        for (int i = 0; i < 8; i++) { ts += sh[0][i]; ts2 += sh[1][i]; }
        atomicAdd(&g_red[0], (double)ts);
        atomicAdd(&g_red[1], (double)ts2);
    }
}

// fused LN2 + PReLU + mean-pool scatter (stats derived inline from g_red)
__global__ void k_pool_ln(const float* __restrict__ lnw, const float* __restrict__ lnb,
                          const float* __restrict__ alpha) {
    int t = blockIdx.x * blockDim.x + threadIdx.x;
    int n = t >> 5;
    if (n >= N_NODES) return;
    int lane = t & 31;
    double NC = (double)N_NODES * (double)HID;
    double mean_d = g_red[0] / NC;
    double var_d  = g_red[1] / NC - mean_d * mean_d;
    float mean = (float)mean_d;
    float inv  = 1.0f / ((float)sqrt(var_d > 0.0 ? var_d : 0.0) + LN_EPS);
    float a = *alpha;
    int4 v = ((const int4*)(g_agg + (size_t)n * HID))[lane];
    const __half2* h = (const __half2*)&v;
    const float4* w4 = (const float4*)(lnw + lane * 8);
    const float4* b4 = (const float4*)(lnb + lane * 8);
    float4 w0 = w4[0], w1 = w4[1];
    float4 c0 = b4[0], c1 = b4[1];
    float x[8];
    #pragma unroll
    for (int i = 0; i < 4; i++) {
        float2 f = __half22float2(h[i]);
        x[2 * i] = f.x; x[2 * i + 1] = f.y;
    }
    float r[8];
    r[0] = (x[0] - mean) * inv * w0.x + c0.x;
    r[1] = (x[1] - mean) * inv * w0.y + c0.y;
    r[2] = (x[2] - mean) * inv * w0.z + c0.z;
    r[3] = (x[3] - mean) * inv * w0.w + c0.w;
    r[4] = (x[4] - mean) * inv * w1.x + c1.x;
    r[5] = (x[5] - mean) * inv * w1.y + c1.y;
    r[6] = (x[6] - mean) * inv * w1.z + c1.z;
    r[7] = (x[7] - mean) * inv * w1.w + c1.w;
    #pragma unroll
    for (int i = 0; i < 8; i++) r[i] = (r[i] >= 0.0f) ? r[i] : a * r[i];
    float4* p = (float4*)(g_pooled + (size_t)g_batch[n] * HID + lane * 8);
    red_add_v4(p,     r[0], r[1], r[2], r[3]);
    red_add_v4(p + 1, r[4], r[5], r[6], r[7]);
    if (lane == 0) atomicAdd(&g_cnt[g_batch[n]], 1.0f);
}

// ---------------- pooled MLP --------------------------------------------------
__global__ void k_lin1(const float* __restrict__ W, const float* __restrict__ bias) {
    int t = blockIdx.x * blockDim.x + threadIdx.x;   // 512*128
    int g = t >> 7, j = t & 127;
    const float* row = g_pooled + (size_t)g * HID;
    float s = 0.0f;
    #pragma unroll 8
    for (int c = 0; c < HID; c++) s += row[c] * W[(size_t)c * MIDC + j];
    g_mid[t] = s / fmaxf(g_cnt[g], 1.0f) + bias[j];
}

__global__ void k_ln_mid(const float* __restrict__ w, const float* __restrict__ b,
                         const float* __restrict__ alpha) {
    const int n = N_GRAPHS * MIDC;
    float a = *alpha;
    float s = 0.0f, s2 = 0.0f;
    for (int i = threadIdx.x; i < n; i += blockDim.x) {
        float v = g_mid[i]; s += v; s2 += v * v;
    }
    for (int o = 16; o > 0; o >>= 1) {
        s  += __shfl_xor_sync(0xffffffffu, s,  o);
        s2 += __shfl_xor_sync(0xffffffffu, s2, o);
    }
    __shared__ float sh[2][32];
    __shared__ float mstd[2];
    int wr = threadIdx.x >> 5, l = threadIdx.x & 31;
    if (l == 0) { sh[0][wr] = s; sh[1][wr] = s2; }
    __syncthreads();
    if (threadIdx.x == 0) {
        float ts = 0.0f, ts2 = 0.0f;
        int nw = blockDim.x >> 5;
        for (int i = 0; i < nw; i++) { ts += sh[0][i]; ts2 += sh[1][i]; }
        float mean = ts / n;
        float var  = ts2 / n - mean * mean;
        mstd[0] = mean;
        mstd[1] = 1.0f / (sqrtf(fmaxf(var, 0.0f)) + LN_EPS);
    }
    __syncthreads();
    float mean = mstd[0], inv = mstd[1];
    for (int i = threadIdx.x; i < n; i += blockDim.x) {
        int c = i & (MIDC - 1);
        float v = (g_mid[i] - mean) * inv * w[c] + b[c];
        g_mid[i] = (v >= 0.0f) ? v : a * v;
    }
}

__global__ void k_lin2(const float* __restrict__ W, const float* __restrict__ bias,
                       float* __restrict__ out) {
    int t = blockIdx.x * blockDim.x + threadIdx.x;   // 512*16
    int g = t >> 4, o = t & 15;
    const float* row = g_mid + (size_t)g * MIDC;
    float s = 0.0f;
    #pragma unroll 8
    for (int j = 0; j < MIDC; j++) s += row[j] * W[(size_t)j * OUTC + o];
    out[t] = s + bias[o];
}

// ---------------- launch -----------------------------------------------------
extern "C" void kernel_launch(void* const* d_in, const int* in_sizes, int n_in,
                              void* d_out, int out_size) {
    const float* pos    = (const float*)d_in[0];
    const void*  ei     = d_in[1];
    const void*  batch  = d_in[2];
    const float* w_conv1 = (const float*)d_in[3];
    const float* b_conv1 = (const float*)d_in[4];
    const float* ln1_w   = (const float*)d_in[5];
    const float* ln1_b   = (const float*)d_in[6];
    const float* a1      = (const float*)d_in[7];
    const float* w_conv2 = (const float*)d_in[8];
    const float* b_conv2 = (const float*)d_in[9];
    const float* ln2_w   = (const float*)d_in[10];
    const float* ln2_b   = (const float*)d_in[11];
    const float* a2      = (const float*)d_in[12];
    const float* w_lin1  = (const float*)d_in[13];
    const float* b_lin1  = (const float*)d_in[14];
    const float* lnm_w   = (const float*)d_in[15];
    const float* lnm_b   = (const float*)d_in[16];
    const float* am      = (const float*)d_in[17];
    const float* w_lin2  = (const float*)d_in[18];
    const float* b_lin2  = (const float*)d_in[19];
    float* out = (float*)d_out;

    // init + dtype detect + histogram + batch conversion
    k_init<<<(2 * N_NODES + 255) / 256, 256>>>();
    k_detect<<<16, 256>>>((const unsigned int*)ei);
    k_hist<<<(N_EDGES / 2 + 255) / 256, 256>>>(ei);
    k_cvt_batch<<<(N_NODES + 255) / 256, 256>>>(batch);

    // CSR build (dinv fused into scan) + rank-2 layer-1 aggregation
    k_scan_block<<<NBLK, 256>>>();
    k_scan_top<<<1, 512>>>();
    k_scan_add<<<NBLK, 256>>>();
    k_scatter<<<(N_EDGES / 2 + 255) / 256, 256>>>(ei, pos);
    k_selfq<<<NBLK, 256>>>(pos);

    // layer 1: analytic LN stats -> fused affine constants
    k_stats1<<<1, 256>>>(w_conv1, b_conv1, ln1_w, ln1_b);

    // layer 2: GEMM with fused A generation, then fp16 CSR aggregation
    k_gemm<<<dim3((N_NODES + 127) / 128, 2), 256>>>(w_conv2, a1);
    k_agg2<<<(N_NODES * 32) / 256, 256>>>(b_conv2);

    // fused LN2 + PReLU + pooling, then MLP
    k_pool_ln<<<(N_NODES * 32 + 255) / 256, 256>>>(ln2_w, ln2_b, a2);
    k_lin1<<<(N_GRAPHS * MIDC) / 256, 256>>>(w_lin1, b_lin1);
    k_ln_mid<<<1, 1024>>>(lnm_w, lnm_b, am);
    k_lin2<<<(N_GRAPHS * OUTC) / 256, 256>>>(w_lin2, b_lin2, out);
}

// round 17
// speedup vs baseline: 1.0926x; 1.0670x over previous
#include <cuda_runtime.h>
#include <cuda_fp16.h>
#include <math.h>
#include <stdint.h>

#define N_NODES  100000
#define N_EDGES  3200000
#define N_GRAPHS 512
#define HID      256
#define MIDC     128
#define OUTC     16
#define LN_EPS   1e-5f
#define NBLK     391                    // ceil(N_NODES/256)

// ---------------- scratch (device globals) -----------------------------------
__device__ __align__(16) __half g_hh[(size_t)N_NODES * HID];   // gemm output (fp16)
__device__ __align__(16) __half g_agg[(size_t)N_NODES * HID];  // layer-2 agg (fp16)
__device__ float  g_dinv[N_NODES];
__device__ int    g_degi[N_NODES];
__device__ int    g_cur[N_NODES];
__device__ int    g_off[N_NODES + 1];
__device__ int    g_bsum[NBLK];
__device__ int    g_boff[NBLK];
__device__ int    g_esrc[N_EDGES];            // src ids, sorted by dst
__device__ float  g_A[2 * N_NODES];           // rank-2 aggregate (layer 1)
__device__ double g_mA[5];                    // SA0,SA1,S00,S11,S01
__device__ __align__(16) float g_c0[HID];     // fused layer-1 affine constants
__device__ __align__(16) float g_c1[HID];
__device__ __align__(16) float g_c2[HID];
__device__ double g_red[2];                   // sum, sumsq (layer 2 LN)
__device__ __align__(16) float  g_pooled[N_GRAPHS * HID];
__device__ float  g_cnt[N_GRAPHS];
__device__ float  g_mid[N_GRAPHS * MIDC];
__device__ int    g_flag;                     // 1 = int32 input, 0 = int64

// ---------------- helpers ----------------------------------------------------
__device__ __forceinline__ void red_add_v4(float4* p, float x, float y, float z, float w) {
    asm volatile("red.global.add.v4.f32 [%0], {%1,%2,%3,%4};"
                 :: "l"(p), "f"(x), "f"(y), "f"(z), "f"(w) : "memory");
}
__device__ __forceinline__ int clampi(int v, int hi) {
    return v < 0 ? 0 : (v >= hi ? hi - 1 : v);
}
__device__ __forceinline__ void mma_f16(float* c, const uint32_t* a, const uint32_t* b) {
    asm("mma.sync.aligned.m16n8k16.row.col.f32.f16.f16.f32 "
        "{%0,%1,%2,%3}, {%4,%5,%6,%7}, {%8,%9}, {%0,%1,%2,%3};"
        : "+f"(c[0]), "+f"(c[1]), "+f"(c[2]), "+f"(c[3])
        : "r"(a[0]), "r"(a[1]), "r"(a[2]), "r"(a[3]), "r"(b[0]), "r"(b[1]));
}
// packed dual-FMA (sm_100+): c = a*b + c on two fp32 lanes
__device__ __forceinline__ void ffma2(float2& c, float2 a, float2 b) {
    unsigned long long cc = *(unsigned long long*)&c;
    unsigned long long aa = *(unsigned long long*)&a;
    unsigned long long bb = *(unsigned long long*)&b;
    asm("fma.rn.f32x2 %0, %1, %2, %3;" : "=l"(cc) : "l"(aa), "l"(bb), "l"(cc));
    c = *(float2*)&cc;
}

// ---------------- init / dtype / conversion ----------------------------------
__global__ void k_init() {
    int i = blockIdx.x * blockDim.x + threadIdx.x;
    if (i == 0) { g_flag = 0; g_red[0] = 0.0; g_red[1] = 0.0;
                  for (int k = 0; k < 5; k++) g_mA[k] = 0.0; }
    if (i < N_NODES) { g_degi[i] = 0; g_cur[i] = 0; }
    if (i < N_GRAPHS * HID) g_pooled[i] = 0.0f;
    if (i < N_GRAPHS) g_cnt[i] = 0.0f;
}

__global__ void k_detect(const unsigned int* __restrict__ w) {
    int t = blockIdx.x * blockDim.x + threadIdx.x;         // 4096 threads
    long long idx = (long long)t * ((long long)N_EDGES / 4096);
    if (w[idx | 1] != 0u) atomicOr(&g_flag, 1);
}

// degree histogram, 2 edges/thread (decodes dst only)
__global__ void k_hist(const void* __restrict__ ei) {
    int i = blockIdx.x * blockDim.x + threadIdx.x;         // N_EDGES/2 threads
    if (i >= N_EDGES / 2) return;
    int d0, d1;
    if (g_flag) {
        int2 v = ((const int2*)((const int*)ei + N_EDGES))[i];
        d0 = v.x; d1 = v.y;
    } else {
        longlong2 v = ((const longlong2*)((const long long*)ei + N_EDGES))[i];
        d0 = (int)v.x; d1 = (int)v.y;
    }
    atomicAdd(&g_degi[clampi(d0, N_NODES)], 1);
    atomicAdd(&g_degi[clampi(d1, N_NODES)], 1);
}

// ---------------- CSR build (dinv fused into block scan) ----------------------
__global__ void k_scan_block() {
    __shared__ int sh[256];
    int t = threadIdx.x, i = blockIdx.x * 256 + t;
    int v = (i < N_NODES) ? g_degi[i] : 0;
    sh[t] = v; __syncthreads();
    for (int o = 1; o < 256; o <<= 1) {
        int x = (t >= o) ? sh[t - o] : 0;
        __syncthreads(); sh[t] += x; __syncthreads();
    }
    if (i < N_NODES) {
        g_off[i]  = sh[t] - v;
        g_dinv[i] = rsqrtf((float)v + 1.0f);     // +1: self loop
    }
    if (t == 255) g_bsum[blockIdx.x] = sh[255];
}

__global__ void k_scan_top() {
    __shared__ int sh[512];
    int t = threadIdx.x;
    int v = (t < NBLK) ? g_bsum[t] : 0;
    sh[t] = v; __syncthreads();
    for (int o = 1; o < 512; o <<= 1) {
        int x = (t >= o) ? sh[t - o] : 0;
        __syncthreads(); sh[t] += x; __syncthreads();
    }
    if (t < NBLK) g_boff[t] = sh[t] - v;
}

__global__ void k_scan_add() {
    int i = blockIdx.x * blockDim.x + threadIdx.x;
    if (i < N_NODES) g_off[i] += g_boff[i >> 8];
    if (i == 0) g_off[N_NODES] = N_EDGES;
}

// scatter edge permutation (src only) by dst, 2 edges/thread. No g_A atomics.
__global__ void k_scatter(const void* __restrict__ ei) {
    int i = blockIdx.x * blockDim.x + threadIdx.x;         // N_EDGES/2 threads
    if (i >= N_EDGES / 2) return;
    int s0, s1, d0, d1;
    if (g_flag) {
        const int* p = (const int*)ei;
        int2 sv = ((const int2*)p)[i];
        int2 dv = ((const int2*)(p + N_EDGES))[i];
        s0 = sv.x; s1 = sv.y; d0 = dv.x; d1 = dv.y;
    } else {
        const long long* p = (const long long*)ei;
        longlong2 sv = ((const longlong2*)p)[i];
        longlong2 dv = ((const longlong2*)(p + N_EDGES))[i];
        s0 = (int)sv.x; s1 = (int)sv.y; d0 = (int)dv.x; d1 = (int)dv.y;
    }
    s0 = clampi(s0, N_NODES); d0 = clampi(d0, N_NODES);
    s1 = clampi(s1, N_NODES); d1 = clampi(d1, N_NODES);
    g_esrc[g_off[d0] + atomicAdd(&g_cur[d0], 1)] = s0;
    g_esrc[g_off[d1] + atomicAdd(&g_cur[d1], 1)] = s1;
}

// rank-2 layer-1 aggregation from CSR: exact, atomic-free (warp per node)
__global__ void k_accA(const float* __restrict__ pos) {
    int t = blockIdx.x * blockDim.x + threadIdx.x;
    int n = t >> 5;                                // 12500 blocks exact
    int lane = t & 31;
    float dn = g_dinv[n];
    float a0 = 0.f, a1 = 0.f;
    int e1 = g_off[n + 1];
    for (int e = g_off[n] + lane; e < e1; e += 32) {
        int s = g_esrc[e];
        float nrm = g_dinv[s] * dn;
        float2 p = ((const float2*)pos)[s];
        a0 += nrm * p.x;
        a1 += nrm * p.y;
    }
    for (int o = 16; o > 0; o >>= 1) {
        a0 += __shfl_xor_sync(0xffffffffu, a0, o);
        a1 += __shfl_xor_sync(0xffffffffu, a1, o);
    }
    if (lane == 0) {
        g_A[2 * n + 0] = a0;
        g_A[2 * n + 1] = a1;
    }
}

// self-loop term + node-moment reduction (fused)
__global__ void k_selfq(const float* __restrict__ pos) {
    int n = blockIdx.x * blockDim.x + threadIdx.x;
    float a0 = 0.f, a1 = 0.f;
    if (n < N_NODES) {
        float d = g_dinv[n], d2 = d * d;
        a0 = g_A[2 * n + 0] + d2 * pos[2 * n];
        a1 = g_A[2 * n + 1] + d2 * pos[2 * n + 1];
        g_A[2 * n + 0] = a0;
        g_A[2 * n + 1] = a1;
    }
    __shared__ float sh[5][256];
    int t = threadIdx.x;
    sh[0][t] = a0; sh[1][t] = a1; sh[2][t] = a0 * a0; sh[3][t] = a1 * a1; sh[4][t] = a0 * a1;
    __syncthreads();
    for (int o = 128; o > 0; o >>= 1) {
        if (t < o)
            for (int k = 0; k < 5; k++) sh[k][t] += sh[k][t + o];
        __syncthreads();
    }
    if (t == 0)
        for (int k = 0; k < 5; k++) atomicAdd(&g_mA[k], (double)sh[k][0]);
}

// ---------------- layer 1: analytic LN stats + fused affine constants --------
__global__ void k_stats1(const float* __restrict__ w, const float* __restrict__ b,
                         const float* __restrict__ lnw, const float* __restrict__ lnb) {
    __shared__ double sh[9][256];
    __shared__ float mstd[2];
    int c = threadIdx.x;
    double w0 = w[c], w1 = w[c + HID], bc = b[c];
    sh[0][c] = bc;        sh[1][c] = bc * bc;
    sh[2][c] = w0;        sh[3][c] = w1;
    sh[4][c] = w0 * w0;   sh[5][c] = w1 * w1;
    sh[6][c] = w0 * w1;   sh[7][c] = bc * w0;   sh[8][c] = bc * w1;
    __syncthreads();
    for (int o = 128; o > 0; o >>= 1) {
        if (c < o)
            for (int k = 0; k < 9; k++) sh[k][c] += sh[k][c + o];
        __syncthreads();
    }
    if (c == 0) {
        double Sb = sh[0][0], Sb2 = sh[1][0], SW0 = sh[2][0], SW1 = sh[3][0];
        double SW0q = sh[4][0], SW1q = sh[5][0], SW01 = sh[6][0];
        double SbW0 = sh[7][0], SbW1 = sh[8][0];
        double SA0 = g_mA[0], SA1 = g_mA[1], S00 = g_mA[2], S11 = g_mA[3], S01 = g_mA[4];
        double Nn = (double)N_NODES, NC = Nn * (double)HID;
        double sum = Nn * Sb + SA0 * SW0 + SA1 * SW1;
        double ss  = Nn * Sb2 + S00 * SW0q + S11 * SW1q
                   + 2.0 * (SA0 * SbW0 + SA1 * SbW1 + S01 * SW01);
        double mean = sum / NC;
        double var  = ss / NC - mean * mean;
        mstd[0] = (float)mean;
        mstd[1] = 1.0f / ((float)sqrt(var > 0.0 ? var : 0.0) + LN_EPS);
    }
    __syncthreads();
    float mean = mstd[0], inv = mstd[1];
    float lw = lnw[c], lb = lnb[c];
    g_c0[c] = ((float)b[c] - mean) * inv * lw + lb;
    g_c1[c] = (float)w[c]       * inv * lw;
    g_c2[c] = (float)w[c + HID] * inv * lw;
}

// ---------------- layer 2: fp16 tensor-core GEMM with fused A generation -----
// B tile prefetched to registers one k-step ahead (latency hidden under MMA).
__global__ void k_gemm(const float* __restrict__ W, const float* __restrict__ alpha) {
    __shared__ __half As[128][24];
    __shared__ __half Bs[128][24];
    const int M = N_NODES;
    const int t = threadIdx.x;
    const int lane = t & 31, warp = t >> 5;
    const int wr = warp >> 1, wc = warp & 1;
    const int g = lane >> 2, tig = lane & 3;
    const int bm = blockIdx.x * 128, bn = blockIdx.y * 128;

    float c[2][8][4];
    #pragma unroll
    for (int i = 0; i < 2; i++)
        #pragma unroll
        for (int j = 0; j < 8; j++)
            #pragma unroll
            for (int r = 0; r < 4; r++) c[i][j][r] = 0.0f;

    const int am = t >> 1, ak = (t & 1) * 8;
    const int bkk = t >> 4, bc = (t & 15) * 8;

    const int gr = bm + am;
    float A0 = 0.f, A1 = 0.f;
    if (gr < M) { A0 = g_A[2 * gr]; A1 = g_A[2 * gr + 1]; }
    const float pa = *alpha;

    // prefetch B tile for k0 = 0
    float4 wv0, wv1;
    {
        const float4* p = (const float4*)(W + (size_t)bkk * 256 + bn + bc);
        wv0 = p[0]; wv1 = p[1];
    }

    for (int k0 = 0; k0 < 256; k0 += 16) {
        // stage A: generate 8 channels from affine constants + prelu
        {
            const float4* C0 = (const float4*)(g_c0 + k0 + ak);
            const float4* C1 = (const float4*)(g_c1 + k0 + ak);
            const float4* C2 = (const float4*)(g_c2 + k0 + ak);
            float v[8];
            float4 x0 = C0[0], x1 = C0[1];
            float4 y0 = C1[0], y1 = C1[1];
            float4 z0 = C2[0], z1 = C2[1];
            v[0] = x0.x + A0 * y0.x + A1 * z0.x;
            v[1] = x0.y + A0 * y0.y + A1 * z0.y;
            v[2] = x0.z + A0 * y0.z + A1 * z0.z;
            v[3] = x0.w + A0 * y0.w + A1 * z0.w;
            v[4] = x1.x + A0 * y1.x + A1 * z1.x;
            v[5] = x1.y + A0 * y1.y + A1 * z1.y;
            v[6] = x1.z + A0 * y1.z + A1 * z1.z;
            v[7] = x1.w + A0 * y1.w + A1 * z1.w;
            #pragma unroll
            for (int i = 0; i < 8; i++) v[i] = (v[i] >= 0.f) ? v[i] : pa * v[i];
            __half2 h[4];
            #pragma unroll
            for (int i = 0; i < 4; i++) h[i] = __floats2half2_rn(v[2 * i], v[2 * i + 1]);
            *(int4*)&As[am][ak] = *(const int4*)h;
        }
        // stage B from prefetched registers (transposed: Bs[n][k])
        {
            Bs[bc + 0][bkk] = __float2half(wv0.x);
            Bs[bc + 1][bkk] = __float2half(wv0.y);
            Bs[bc + 2][bkk] = __float2half(wv0.z);
            Bs[bc + 3][bkk] = __float2half(wv0.w);
            Bs[bc + 4][bkk] = __float2half(wv1.x);
            Bs[bc + 5][bkk] = __float2half(wv1.y);
            Bs[bc + 6][bkk] = __float2half(wv1.z);
            Bs[bc + 7][bkk] = __float2half(wv1.w);
        }
        __syncthreads();
        // prefetch next B tile while tensor cores work
        if (k0 + 16 < 256) {
            const float4* p = (const float4*)(W + (size_t)(k0 + 16 + bkk) * 256 + bn + bc);
            wv0 = p[0]; wv1 = p[1];
        }
        uint32_t a[2][4], b[8][2];
        #pragma unroll
        for (int i = 0; i < 2; i++) {
            int r0 = wr * 32 + i * 16 + g;
            a[i][0] = *(const uint32_t*)&As[r0][2 * tig];
            a[i][1] = *(const uint32_t*)&As[r0 + 8][2 * tig];
            a[i][2] = *(const uint32_t*)&As[r0][2 * tig + 8];
            a[i][3] = *(const uint32_t*)&As[r0 + 8][2 * tig + 8];
        }
        #pragma unroll
        for (int j = 0; j < 8; j++) {
            int cb = wc * 64 + j * 8 + g;
            b[j][0] = *(const uint32_t*)&Bs[cb][2 * tig];
            b[j][1] = *(const uint32_t*)&Bs[cb][2 * tig + 8];
        }
        #pragma unroll
        for (int i = 0; i < 2; i++)
            #pragma unroll
            for (int j = 0; j < 8; j++)
                mma_f16(c[i][j], a[i], b[j]);
        __syncthreads();
    }
    #pragma unroll
    for (int i = 0; i < 2; i++) {
        int r0 = bm + wr * 32 + i * 16 + g;
        int r1 = r0 + 8;
        #pragma unroll
        for (int j = 0; j < 8; j++) {
            int col = bn + wc * 64 + j * 8 + 2 * tig;
            if (r0 < M)
                *(__half2*)(g_hh + (size_t)r0 * 256 + col) = __floats2half2_rn(c[i][j][0], c[i][j][1]);
            if (r1 < M)
                *(__half2*)(g_hh + (size_t)r1 * 256 + col) = __floats2half2_rn(c[i][j][2], c[i][j][3]);
        }
    }
}

// CSR aggregation: warp per node, 4-edge unrolled gather (MLP=4),
// fp16 gather, f32x2 accum, fp16 out, LN stats epilogue
__global__ void k_agg2(const float* __restrict__ bias) {
    int t = blockIdx.x * blockDim.x + threadIdx.x;
    int n = t >> 5;                              // 12500 blocks x 8 warps exact
    int lane = t & 31;
    float dn = g_dinv[n];
    float2 acc[4];
    {
        const float4* b4 = (const float4*)(bias + lane * 8);
        float4 x = b4[0], y = b4[1];
        acc[0] = make_float2(x.x, x.y); acc[1] = make_float2(x.z, x.w);
        acc[2] = make_float2(y.x, y.y); acc[3] = make_float2(y.z, y.w);
    }
    {   // self loop
        float d2 = dn * dn;
        float2 d2v = make_float2(d2, d2);
        int4 v = ((const int4*)(g_hh + (size_t)n * HID))[lane];
        const __half2* h = (const __half2*)&v;
        #pragma unroll
        for (int i = 0; i < 4; i++) ffma2(acc[i], __half22float2(h[i]), d2v);
    }
    int e = g_off[n], e1 = g_off[n + 1];
    for (; e + 3 < e1; e += 4) {                 // 4 independent gathers in flight
        int sa = g_esrc[e],     sb = g_esrc[e + 1];
        int sc = g_esrc[e + 2], sd = g_esrc[e + 3];
        int4 va = ((const int4*)(g_hh + (size_t)sa * HID))[lane];
        int4 vb = ((const int4*)(g_hh + (size_t)sb * HID))[lane];
        int4 vc = ((const int4*)(g_hh + (size_t)sc * HID))[lane];
        int4 vd = ((const int4*)(g_hh + (size_t)sd * HID))[lane];
        float fa = g_dinv[sa] * dn, fb = g_dinv[sb] * dn;
        float fc = g_dinv[sc] * dn, fd = g_dinv[sd] * dn;
        float2 fa2 = make_float2(fa, fa), fb2 = make_float2(fb, fb);
        float2 fc2 = make_float2(fc, fc), fd2 = make_float2(fd, fd);
        const __half2* ha = (const __half2*)&va;
        const __half2* hb = (const __half2*)&vb;
        const __half2* hc = (const __half2*)&vc;
        const __half2* hd = (const __half2*)&vd;
        #pragma unroll
        for (int i = 0; i < 4; i++) {
            ffma2(acc[i], __half22float2(ha[i]), fa2);
            ffma2(acc[i], __half22float2(hb[i]), fb2);
            ffma2(acc[i], __half22float2(hc[i]), fc2);
            ffma2(acc[i], __half22float2(hd[i]), fd2);
        }
    }
    for (; e < e1; e++) {
        int sa = g_esrc[e];
        float fa = g_dinv[sa] * dn;
        float2 fa2 = make_float2(fa, fa);
        int4 va = ((const int4*)(g_hh + (size_t)sa * HID))[lane];
        const __half2* ha = (const __half2*)&va;
        #pragma unroll
        for (int i = 0; i < 4; i++) ffma2(acc[i], __half22float2(ha[i]), fa2);
    }
    {   // write agg as fp16
        __half2 h[4];
        #pragma unroll
        for (int i = 0; i < 4; i++) h[i] = __floats2half2_rn(acc[i].x, acc[i].y);
        ((int4*)(g_agg + (size_t)n * HID))[lane] = *(const int4*)h;
    }
    float s = 0.f, s2 = 0.f;
    #pragma unroll
    for (int i = 0; i < 4; i++) {
        s  += acc[i].x + acc[i].y;
        s2 += acc[i].x * acc[i].x + acc[i].y * acc[i].y;
    }
    for (int o = 16; o > 0; o >>= 1) {
        s  += __shfl_xor_sync(0xffffffffu, s,  o);
        s2 += __shfl_xor_sync(0xffffffffu, s2, o);
    }
    __shared__ float sh[2][8];
    int w = threadIdx.x >> 5;
    if (lane == 0) { sh[0][w] = s; sh[1][w] = s2; }
    __syncthreads();
    if (threadIdx.x == 0) {
        float ts = 0.f, ts2 = 0.f;
        #pragma unroll
        for (int i = 0; i < 8; i++) { ts += sh[0][i]; ts2 += sh[1][i]; }
        atomicAdd(&g_red[0], (double)ts);
        atomicAdd(&g_red[1], (double)ts2);
    }
}

// fused LN2 + PReLU + mean-pool scatter; batch ids decoded inline
__global__ void k_pool_ln(const void* __restrict__ batch,
                          const float* __restrict__ lnw, const float* __restrict__ lnb,
                          const float* __restrict__ alpha) {
    int t = blockIdx.x * blockDim.x + threadIdx.x;
    int n = t >> 5;
    if (n >= N_NODES) return;
    int lane = t & 31;
    double NC = (double)N_NODES * (double)HID;
    double mean_d = g_red[0] / NC;
    double var_d  = g_red[1] / NC - mean_d * mean_d;
    float mean = (float)mean_d;
    float inv  = 1.0f / ((float)sqrt(var_d > 0.0 ? var_d : 0.0) + LN_EPS);
    float a = *alpha;
    int b = g_flag ? ((const int*)batch)[n] : (int)((const long long*)batch)[n];
    b = clampi(b, N_GRAPHS);
    int4 v = ((const int4*)(g_agg + (size_t)n * HID))[lane];
    const __half2* h = (const __half2*)&v;
    const float4* w4 = (const float4*)(lnw + lane * 8);
    const float4* b4 = (const float4*)(lnb + lane * 8);
    float4 w0 = w4[0], w1 = w4[1];
    float4 c0 = b4[0], c1 = b4[1];
    float x[8];
    #pragma unroll
    for (int i = 0; i < 4; i++) {
        float2 f = __half22float2(h[i]);
        x[2 * i] = f.x; x[2 * i + 1] = f.y;
    }
    float r[8];
    r[0] = (x[0] - mean) * inv * w0.x + c0.x;
    r[1] = (x[1] - mean) * inv * w0.y + c0.y;
    r[2] = (x[2] - mean) * inv * w0.z + c0.z;
    r[3] = (x[3] - mean) * inv * w0.w + c0.w;
    r[4] = (x[4] - mean) * inv * w1.x + c1.x;
    r[5] = (x[5] - mean) * inv * w1.y + c1.y;
    r[6] = (x[6] - mean) * inv * w1.z + c1.z;
    r[7] = (x[7] - mean) * inv * w1.w + c1.w;
    #pragma unroll
    for (int i = 0; i < 8; i++) r[i] = (r[i] >= 0.0f) ? r[i] : a * r[i];
    float4* p = (float4*)(g_pooled + (size_t)b * HID + lane * 8);
    red_add_v4(p,     r[0], r[1], r[2], r[3]);
    red_add_v4(p + 1, r[4], r[5], r[6], r[7]);
    if (lane == 0) atomicAdd(&g_cnt[b], 1.0f);
}

// ---------------- pooled MLP --------------------------------------------------
__global__ void k_lin1(const float* __restrict__ W, const float* __restrict__ bias) {
    int t = blockIdx.x * blockDim.x + threadIdx.x;   // 512*128
    int g = t >> 7, j = t & 127;
    const float* row = g_pooled + (size_t)g * HID;
    float s = 0.0f;
    #pragma unroll 8
    for (int c = 0; c < HID; c++) s += row[c] * W[(size_t)c * MIDC + j];
    g_mid[t] = s / fmaxf(g_cnt[g], 1.0f) + bias[j];
}

__global__ void k_ln_mid(const float* __restrict__ w, const float* __restrict__ b,
                         const float* __restrict__ alpha) {
    const int n = N_GRAPHS * MIDC;
    float a = *alpha;
    float s = 0.0f, s2 = 0.0f;
    for (int i = threadIdx.x; i < n; i += blockDim.x) {
        float v = g_mid[i]; s += v; s2 += v * v;
    }
    for (int o = 16; o > 0; o >>= 1) {
        s  += __shfl_xor_sync(0xffffffffu, s,  o);
        s2 += __shfl_xor_sync(0xffffffffu, s2, o);
    }
    __shared__ float sh[2][32];
    __shared__ float mstd[2];
    int wr = threadIdx.x >> 5, l = threadIdx.x & 31;
    if (l == 0) { sh[0][wr] = s; sh[1][wr] = s2; }
    __syncthreads();
    if (threadIdx.x == 0) {
        float ts = 0.0f, ts2 = 0.0f;
        int nw = blockDim.x >> 5;
        for (int i = 0; i < nw; i++) { ts += sh[0][i]; ts2 += sh[1][i]; }
        float mean = ts / n;
        float var  = ts2 / n - mean * mean;
        mstd[0] = mean;
        mstd[1] = 1.0f / (sqrtf(fmaxf(var, 0.0f)) + LN_EPS);
    }
    __syncthreads();
    float mean = mstd[0], inv = mstd[1];
    for (int i = threadIdx.x; i < n; i += blockDim.x) {
        int c = i & (MIDC - 1);
        float v = (g_mid[i] - mean) * inv * w[c] + b[c];
        g_mid[i] = (v >= 0.0f) ? v : a * v;
    }
}

__global__ void k_lin2(const float* __restrict__ W, const float* __restrict__ bias,
                       float* __restrict__ out) {
    int t = blockIdx.x * blockDim.x + threadIdx.x;   // 512*16
    int g = t >> 4, o = t & 15;
    const float* row = g_mid + (size_t)g * MIDC;
    float s = 0.0f;
    #pragma unroll 8
    for (int j = 0; j < MIDC; j++) s += row[j] * W[(size_t)j * OUTC + o];
    out[t] = s + bias[o];
}

// ---------------- launch -----------------------------------------------------
extern "C" void kernel_launch(void* const* d_in, const int* in_sizes, int n_in,
                              void* d_out, int out_size) {
    const float* pos    = (const float*)d_in[0];
    const void*  ei     = d_in[1];
    const void*  batch  = d_in[2];
    const float* w_conv1 = (const float*)d_in[3];
    const float* b_conv1 = (const float*)d_in[4];
    const float* ln1_w   = (const float*)d_in[5];
    const float* ln1_b   = (const float*)d_in[6];
    const float* a1      = (const float*)d_in[7];
    const float* w_conv2 = (const float*)d_in[8];
    const float* b_conv2 = (const float*)d_in[9];
    const float* ln2_w   = (const float*)d_in[10];
    const float* ln2_b   = (const float*)d_in[11];
    const float* a2      = (const float*)d_in[12];
    const float* w_lin1  = (const float*)d_in[13];
    const float* b_lin1  = (const float*)d_in[14];
    const float* lnm_w   = (const float*)d_in[15];
    const float* lnm_b   = (const float*)d_in[16];
    const float* am      = (const float*)d_in[17];
    const float* w_lin2  = (const float*)d_in[18];
    const float* b_lin2  = (const float*)d_in[19];
    float* out = (float*)d_out;

    // init + dtype detect + histogram
    k_init<<<(N_GRAPHS * HID + 255) / 256, 256>>>();
    k_detect<<<16, 256>>>((const unsigned int*)ei);
    k_hist<<<(N_EDGES / 2 + 255) / 256, 256>>>(ei);

    // CSR build (dinv fused into scan); scatter = permutation only
    k_scan_block<<<NBLK, 256>>>();
    k_scan_top<<<1, 512>>>();
    k_scan_add<<<NBLK, 256>>>();
    k_scatter<<<(N_EDGES / 2 + 255) / 256, 256>>>(ei);

    // rank-2 layer-1 aggregation from CSR (atomic-free) + self loop + moments
    k_accA<<<(N_NODES * 32) / 256, 256>>>(pos);
    k_selfq<<<NBLK, 256>>>(pos);

    // layer 1: analytic LN stats -> fused affine constants
    k_stats1<<<1, 256>>>(w_conv1, b_conv1, ln1_w, ln1_b);

    // layer 2: GEMM (B reg-prefetch) + fp16 CSR aggregation
    k_gemm<<<dim3((N_NODES + 127) / 128, 2), 256>>>(w_conv2, a1);
    k_agg2<<<(N_NODES * 32) / 256, 256>>>(b_conv2);

    // fused LN2 + PReLU + pooling (batch decoded inline), then MLP
    k_pool_ln<<<(N_NODES * 32 + 255) / 256, 256>>>(batch, ln2_w, ln2_b, a2);
    k_lin1<<<(N_GRAPHS * MIDC) / 256, 256>>>(w_lin1, b_lin1);
    k_ln_mid<<<1, 1024>>>(lnm_w, lnm_b, am);
    k_lin2<<<(N_GRAPHS * OUTC) / 256, 256>>>(w_lin2, b_lin2, out);
}